// round 1
// baseline (speedup 1.0000x reference)
#include <cuda_runtime.h>
#include <math.h>

// ---------------------------------------------------------------------------
// Encoder_84413287236054 : fp32 transformer encoder layer
// B=2, S=2048, D=1024, H=16, hd=64, DFF=4096
// Round 1: correct fp32 SIMT baseline (FMA-pipe bound). Tensor-core port next.
// ---------------------------------------------------------------------------

#define TOK  4096      // B*S
#define DIM  1024
#define DFF  4096
#define NH   16
#define HD   64
#define SEQ  2048
#define BATCH 2

// Scratch (allocation-free: __device__ globals)
__device__ float g_h   [TOK * DIM];   // LN1 output
__device__ float g_q   [TOK * DIM];
__device__ float g_k   [TOK * DIM];
__device__ float g_v   [TOK * DIM];
__device__ float g_attn[TOK * DIM];   // merged-head attention output
__device__ float g_x1  [TOK * DIM];   // residual-1 output
__device__ float g_h2  [TOK * DIM];   // LN2 output
__device__ float g_ff  [TOK * DFF];   // GELU(FFN1) output

// ---------------------------------------------------------------------------
// LayerNorm: one block per row (1024 cols), 256 threads, float4 per thread.
// ---------------------------------------------------------------------------
__global__ __launch_bounds__(256) void ln_kernel(
    const float* __restrict__ x, const float* __restrict__ g,
    const float* __restrict__ b, float* __restrict__ out)
{
    const int row = blockIdx.x;
    const int t = threadIdx.x;
    const float4 v = ((const float4*)(x + (size_t)row * DIM))[t];

    float s  = v.x + v.y + v.z + v.w;
    float ss = v.x*v.x + v.y*v.y + v.z*v.z + v.w*v.w;
    #pragma unroll
    for (int o = 16; o; o >>= 1) {
        s  += __shfl_xor_sync(0xffffffffu, s,  o);
        ss += __shfl_xor_sync(0xffffffffu, ss, o);
    }
    __shared__ float sm[8], sm2[8];
    if ((t & 31) == 0) { sm[t >> 5] = s; sm2[t >> 5] = ss; }
    __syncthreads();
    float ts = 0.f, tss = 0.f;
    #pragma unroll
    for (int i = 0; i < 8; i++) { ts += sm[i]; tss += sm2[i]; }

    const float mu   = ts * (1.0f / DIM);
    const float var  = tss * (1.0f / DIM) - mu * mu;
    const float rstd = rsqrtf(var + 1e-5f);

    const float4 gv = ((const float4*)g)[t];
    const float4 bv = ((const float4*)b)[t];
    float4 o4;
    o4.x = (v.x - mu) * rstd * gv.x + bv.x;
    o4.y = (v.y - mu) * rstd * gv.y + bv.y;
    o4.z = (v.z - mu) * rstd * gv.z + bv.z;
    o4.w = (v.w - mu) * rstd * gv.w + bv.w;
    ((float4*)(out + (size_t)row * DIM))[t] = o4;
}

// ---------------------------------------------------------------------------
// SGEMM: C[M,N] = A[M,K] @ W[K,N] + bias (+res) (+gelu)
// 128x128x8 tiles, 256 threads, 8x8 microtile, double-buffered smem.
// EPI: 0 = bias, 1 = bias + residual, 2 = bias + exact GELU
// ---------------------------------------------------------------------------
template<int EPI>
__global__ __launch_bounds__(256) void gemm_kernel(
    const float* __restrict__ A, const float* __restrict__ W,
    const float* __restrict__ bias, const float* __restrict__ res,
    float* __restrict__ C, int M, int N, int K)
{
    __shared__ float As[2][8][132];   // transposed A tile, padded
    __shared__ float Ws[2][8][128];

    const int tid = threadIdx.x;
    const int tx = tid & 15;          // 0..15 -> N microtile
    const int ty = tid >> 4;          // 0..15 -> M microtile
    const int ar = tid >> 1, ac = (tid & 1) * 4;   // A tile load coords
    const int wr = tid >> 5, wc = (tid & 31) * 4;  // W tile load coords

    const float* Aptr = A + (size_t)(blockIdx.y * 128 + ar) * K + ac;
    const float* Wptr = W + (size_t)wr * N + blockIdx.x * 128 + wc;

    // stage 0
    float4 av = *(const float4*)Aptr;
    float4 wv = *(const float4*)Wptr;
    As[0][ac + 0][ar] = av.x; As[0][ac + 1][ar] = av.y;
    As[0][ac + 2][ar] = av.z; As[0][ac + 3][ar] = av.w;
    *(float4*)&Ws[0][wr][wc] = wv;
    __syncthreads();

    float acc[8][8] = {};
    const int nk = K >> 3;
    for (int kt = 0; kt < nk; kt++) {
        const int buf = kt & 1;
        if (kt + 1 < nk) {  // prefetch next tile from gmem
            av = *(const float4*)(Aptr + (kt + 1) * 8);
            wv = *(const float4*)(Wptr + (size_t)(kt + 1) * 8 * N);
        }
        #pragma unroll
        for (int kk = 0; kk < 8; kk++) {
            const float4 a0 = *(const float4*)&As[buf][kk][ty * 8];
            const float4 a1 = *(const float4*)&As[buf][kk][ty * 8 + 4];
            const float4 b0 = *(const float4*)&Ws[buf][kk][tx * 8];
            const float4 b1 = *(const float4*)&Ws[buf][kk][tx * 8 + 4];
            const float a[8]  = {a0.x, a0.y, a0.z, a0.w, a1.x, a1.y, a1.z, a1.w};
            const float bb[8] = {b0.x, b0.y, b0.z, b0.w, b1.x, b1.y, b1.z, b1.w};
            #pragma unroll
            for (int i = 0; i < 8; i++)
                #pragma unroll
                for (int j = 0; j < 8; j++)
                    acc[i][j] = fmaf(a[i], bb[j], acc[i][j]);
        }
        if (kt + 1 < nk) {
            const int nb = buf ^ 1;
            As[nb][ac + 0][ar] = av.x; As[nb][ac + 1][ar] = av.y;
            As[nb][ac + 2][ar] = av.z; As[nb][ac + 3][ar] = av.w;
            *(float4*)&Ws[nb][wr][wc] = wv;
            __syncthreads();
        }
    }

    // epilogue
    const int row0 = blockIdx.y * 128 + ty * 8;
    const int col  = blockIdx.x * 128 + tx * 8;
    float br[8];
    *(float4*)&br[0] = *(const float4*)&bias[col];
    *(float4*)&br[4] = *(const float4*)&bias[col + 4];
    #pragma unroll
    for (int i = 0; i < 8; i++) {
        const size_t off = (size_t)(row0 + i) * N + col;
        float t[8];
        #pragma unroll
        for (int j = 0; j < 8; j++) t[j] = acc[i][j] + br[j];
        if (EPI == 1) {
            const float4 r0 = *(const float4*)(res + off);
            const float4 r1 = *(const float4*)(res + off + 4);
            t[0] += r0.x; t[1] += r0.y; t[2] += r0.z; t[3] += r0.w;
            t[4] += r1.x; t[5] += r1.y; t[6] += r1.z; t[7] += r1.w;
        }
        if (EPI == 2) {
            #pragma unroll
            for (int j = 0; j < 8; j++) t[j] = t[j] * normcdff(t[j]);  // exact GELU
        }
        *(float4*)(C + off)     = make_float4(t[0], t[1], t[2], t[3]);
        *(float4*)(C + off + 4) = make_float4(t[4], t[5], t[6], t[7]);
    }
}

// ---------------------------------------------------------------------------
// Attention: grid = (SEQ/128, B*NH). Block = 128 threads; one q-row per
// thread, K/V staged in smem in 64-row tiles, online softmax with
// rare-rescale (max updates ~log(S) times per row).
// q/k/v layout: [token][DIM] where col = h*HD + d.
// ---------------------------------------------------------------------------
__global__ __launch_bounds__(128) void attn_kernel(
    const float* __restrict__ q, const float* __restrict__ k,
    const float* __restrict__ v, float* __restrict__ outp)
{
    __shared__ float Ks[64][68];
    __shared__ float Vs[64][68];

    const int bh = blockIdx.y;
    const int b = bh >> 4, h = bh & 15;
    const int qrow = blockIdx.x * 128 + threadIdx.x;   // within SEQ
    const size_t qoff  = ((size_t)(b * SEQ + qrow)) * DIM + h * HD;
    const size_t kbase = ((size_t)(b * SEQ)) * DIM + h * HD;

    float qr[64];
    #pragma unroll
    for (int i = 0; i < 16; i++) {
        const float4 t = *(const float4*)(q + qoff + i * 4);
        qr[i*4] = t.x; qr[i*4+1] = t.y; qr[i*4+2] = t.z; qr[i*4+3] = t.w;
    }
    float o[64];
    #pragma unroll
    for (int d = 0; d < 64; d++) o[d] = 0.f;
    float m = -1e30f, l = 0.f;

    for (int kt = 0; kt < SEQ / 64; kt++) {
        __syncthreads();   // previous tile fully consumed before overwrite
        #pragma unroll
        for (int it = 0; it < 8; it++) {
            const int idx = it * 128 + threadIdx.x;    // 0..1023
            const int r = idx >> 4, c4 = (idx & 15) * 4;
            const size_t gp = kbase + (size_t)(kt * 64 + r) * DIM + c4;
            *(float4*)&Ks[r][c4] = *(const float4*)(k + gp);
            *(float4*)&Vs[r][c4] = *(const float4*)(v + gp);
        }
        __syncthreads();

        #pragma unroll 2
        for (int j = 0; j < 64; j++) {
            float s = 0.f;
            #pragma unroll
            for (int d4 = 0; d4 < 16; d4++) {
                const float4 kv = *(const float4*)&Ks[j][d4 * 4];
                s = fmaf(qr[d4*4],   kv.x, s);
                s = fmaf(qr[d4*4+1], kv.y, s);
                s = fmaf(qr[d4*4+2], kv.z, s);
                s = fmaf(qr[d4*4+3], kv.w, s);
            }
            s *= 0.125f;   // 1/sqrt(64)
            float p;
            if (s > m) {
                const float corr = __expf(m - s);
                m = s;
                l *= corr;
                #pragma unroll
                for (int d = 0; d < 64; d++) o[d] *= corr;
                p = 1.f;
            } else {
                p = __expf(s - m);
            }
            l += p;
            #pragma unroll
            for (int d4 = 0; d4 < 16; d4++) {
                const float4 vv = *(const float4*)&Vs[j][d4 * 4];
                o[d4*4]   = fmaf(p, vv.x, o[d4*4]);
                o[d4*4+1] = fmaf(p, vv.y, o[d4*4+1]);
                o[d4*4+2] = fmaf(p, vv.z, o[d4*4+2]);
                o[d4*4+3] = fmaf(p, vv.w, o[d4*4+3]);
            }
        }
    }

    const float inv = 1.f / l;
    #pragma unroll
    for (int i = 0; i < 16; i++) {
        float4 t;
        t.x = o[i*4]   * inv; t.y = o[i*4+1] * inv;
        t.z = o[i*4+2] * inv; t.w = o[i*4+3] * inv;
        *(float4*)(outp + qoff + i * 4) = t;
    }
}

// ---------------------------------------------------------------------------
// Launch (graph-capturable: kernel launches only)
// ---------------------------------------------------------------------------
extern "C" void kernel_launch(void* const* d_in, const int* in_sizes, int n_in,
                              void* d_out, int out_size)
{
    const float* x     = (const float*)d_in[0];
    const float* ln1_g = (const float*)d_in[1];
    const float* ln1_b = (const float*)d_in[2];
    const float* wq = (const float*)d_in[3];
    const float* bq = (const float*)d_in[4];
    const float* wk = (const float*)d_in[5];
    const float* bk = (const float*)d_in[6];
    const float* wv = (const float*)d_in[7];
    const float* bv = (const float*)d_in[8];
    const float* wo = (const float*)d_in[9];
    const float* bo = (const float*)d_in[10];
    const float* w1 = (const float*)d_in[11];
    const float* b1 = (const float*)d_in[12];
    const float* w2 = (const float*)d_in[13];
    const float* b2 = (const float*)d_in[14];
    const float* ln2_g = (const float*)d_in[15];
    const float* ln2_b = (const float*)d_in[16];
    float* out = (float*)d_out;

    float *h, *q, *k, *v, *attn, *x1, *h2, *ff;
    cudaGetSymbolAddress((void**)&h,    g_h);
    cudaGetSymbolAddress((void**)&q,    g_q);
    cudaGetSymbolAddress((void**)&k,    g_k);
    cudaGetSymbolAddress((void**)&v,    g_v);
    cudaGetSymbolAddress((void**)&attn, g_attn);
    cudaGetSymbolAddress((void**)&x1,   g_x1);
    cudaGetSymbolAddress((void**)&h2,   g_h2);
    cudaGetSymbolAddress((void**)&ff,   g_ff);

    const dim3 gD(DIM / 128, TOK / 128);   // (8, 32)
    const dim3 gF(DFF / 128, TOK / 128);   // (32, 32)

    ln_kernel<<<TOK, 256>>>(x, ln1_g, ln1_b, h);
    gemm_kernel<0><<<gD, 256>>>(h, wq, bq, nullptr, q, TOK, DIM, DIM);
    gemm_kernel<0><<<gD, 256>>>(h, wk, bk, nullptr, k, TOK, DIM, DIM);
    gemm_kernel<0><<<gD, 256>>>(h, wv, bv, nullptr, v, TOK, DIM, DIM);
    attn_kernel<<<dim3(SEQ / 128, BATCH * NH), 128>>>(q, k, v, attn);
    gemm_kernel<1><<<gD, 256>>>(attn, wo, bo, x, x1, TOK, DIM, DIM);
    ln_kernel<<<TOK, 256>>>(x1, ln2_g, ln2_b, h2);
    gemm_kernel<2><<<gF, 256>>>(h2, w1, b1, nullptr, ff, TOK, DFF, DIM);
    gemm_kernel<1><<<gD, 256>>>(ff, w2, b2, x1, out, TOK, DIM, DFF);
}